// round 16
// baseline (speedup 1.0000x reference)
#include <cuda_runtime.h>
#include <cuda_fp16.h>
#include <cstdint>

#define BB 4
#define CC 256
#define NN 4096
#define STILE 256          // keys per attention tile
#define NTILE (NN / STILE) // 16
#define NCHUNK 4           // k-chunks of 64 per proj tile
#define VSTRIDE 264        // Vt col stride in halves

typedef unsigned long long ull;

// Device-global scratch (no allocations). Q/K stored FRAGMENT-PERMUTED fp16.
// Q (A-frag): [b][mb=row/16][ksg=k/16][lane][4xb32], pre-scaled by 1/16*log2e.
// K (B-frag): [b][block=row/8][ksg][lane][2xb32].
__device__ __half g_Q[BB * NN * CC];
__device__ __half g_K[BB * NN * CC];

__device__ __forceinline__ void cp16(uint32_t dst, const void* src) {
    asm volatile("cp.async.cg.shared.global [%0], [%1], 16;" :: "r"(dst), "l"(src) : "memory");
}

__device__ __forceinline__ uint32_t smem_u32(const void* p) {
    uint32_t a;
    asm("{ .reg .u64 t; cvta.to.shared.u64 t, %1; cvt.u32.u64 %0, t; }" : "=r"(a) : "l"(p));
    return a;
}

__device__ __forceinline__ void mma16(float4& d, const uint4& a, uint32_t b0, uint32_t b1) {
    asm volatile(
        "mma.sync.aligned.m16n8k16.row.col.f32.f16.f16.f32 "
        "{%0,%1,%2,%3}, {%4,%5,%6,%7}, {%8,%9}, {%0,%1,%2,%3};"
        : "+f"(d.x), "+f"(d.y), "+f"(d.z), "+f"(d.w)
        : "r"(a.x), "r"(a.y), "r"(a.z), "r"(a.w), "r"(b0), "r"(b1));
}

__device__ __forceinline__ uint32_t packh2(float x, float y) {
    __half2 h = __floats2half2_rn(x, y);
    return *reinterpret_cast<uint32_t*>(&h);
}

// pack to fp16 pair then single MUFU ex2 on both halves
__device__ __forceinline__ uint32_t ex2h2(float x, float y) {
    __half2 h = __floats2half2_rn(x, y);
    uint32_t u = *reinterpret_cast<uint32_t*>(&h);
    uint32_t r;
    asm("ex2.approx.f16x2 %0, %1;" : "=r"(r) : "r"(u));
    return r;
}

// ---------------------------------------------------------------------------
// Projection via fp16 mma.sync. A fragments built from fp32 feature
// ([c][n] layout, transpose+convert inline); W converted to B-fragments
// inline per chunk (fp32 -> fp16, L2-resident source). Writes Q/K permuted.
// ---------------------------------------------------------------------------
#define P_OFF_AP  0                        // 64KB token fragments
#define P_OFF_WF  65536                    // 32KB W fragment buffer (per chunk)
#define P_SMEM_TOTAL 98304

__global__ __launch_bounds__(512) void proj_mma_kernel(
    const float* __restrict__ feature,
    const float* __restrict__ q_w, const float* __restrict__ q_b,
    const float* __restrict__ k_w, const float* __restrict__ k_b)
{
    extern __shared__ char smem[];
    const int t    = threadIdx.x;
    const int lane = t & 31;
    const int wid  = t >> 5;
    const int wq   = wid >> 3;
    const int wk   = wid & 7;
    const int b    = blockIdx.y;
    const int l0   = blockIdx.x * 128;
    const int which = blockIdx.z;

    uint32_t* Ap32 = (uint32_t*)(smem + P_OFF_AP);
    const uint4* Ap4 = (const uint4*)(smem + P_OFF_AP);
    uint2* Wf = (uint2*)(smem + P_OFF_WF);

    const float*  Fc = feature + (size_t)b * CC * NN;
    const float*  Wsrc = which ? k_w : q_w;
    const float*  bi = which ? k_b : q_b;
    uint32_t* outp = reinterpret_cast<uint32_t*>((which ? g_K : g_Q) + (size_t)b * NN * CC);
    const float   sc = which ? 1.0f : 0.0625f * 1.4426950408889634f;

    // A fragments from raw fp32 feature: element (row, c) -> fragment slot.
    #pragma unroll
    for (int p = 0; p < 32; ++p) {
        int idx = t + p * 512;        // 0..16383
        int row = idx & 127;
        int c   = (idx >> 7) * 2;     // even c; pair (c, c+1) in one half2
        float f0 = Fc[(size_t)c * NN + l0 + row];
        float f1 = Fc[(size_t)(c + 1) * NN + l0 + row];
        int mb = row >> 4;
        int ks = c >> 4;
        int klv = (c & 7) >> 1;
        int khalf = (c & 15) >> 3;
        int lane_st = (row & 7) * 4 + klv;
        int reg = ((row >> 3) & 1) + khalf * 2;
        Ap32[((mb * 16 + ks) * 32 + lane_st) * 4 + reg] = packh2(f0, f1);
    }

    const int r4 = lane >> 2, kl = lane & 3;

    float4 acc[4][4];
    #pragma unroll
    for (int i = 0; i < 4; ++i)
        #pragma unroll
        for (int j = 0; j < 4; ++j)
            acc[i][j] = make_float4(0.f, 0.f, 0.f, 0.f);

    for (int c = 0; c < NCHUNK; ++c) {
        __syncthreads();   // Wf free (prev chunk's MMA done); first iter: no-op

        // Inline W chunk convert: fp32 [d][cc] -> B-fragment fp16 smem.
        // 4096 uint2 slots: slot s -> lane = s&31, ksl = (s>>5)&3, blk = s>>7.
        #pragma unroll
        for (int p = 0; p < 8; ++p) {
            int s = t + p * 512;            // 0..4095
            int lane_s = s & 31;
            int ksl = (s >> 5) & 3;
            int blk = s >> 7;               // 0..31
            int d  = blk * 8 + (lane_s >> 2);
            int cb = c * 64 + ksl * 16 + (lane_s & 3) * 2;
            float2 v0 = *reinterpret_cast<const float2*>(&Wsrc[(size_t)d * CC + cb]);
            float2 v1 = *reinterpret_cast<const float2*>(&Wsrc[(size_t)d * CC + cb + 8]);
            Wf[s] = make_uint2(packh2(v0.x, v0.y), packh2(v1.x, v1.y));
        }
        __syncthreads();   // chunk fragments visible (also covers A-frags at c=0)

        #pragma unroll
        for (int ksl = 0; ksl < 4; ++ksl) {
            const int ksg = c * 4 + ksl;
            uint4 A[4];
            #pragma unroll
            for (int mf = 0; mf < 4; ++mf)
                A[mf] = Ap4[((wq * 4 + mf) * 16 + ksg) * 32 + lane];
            #pragma unroll
            for (int j = 0; j < 4; ++j) {
                uint2 bb = Wf[((wk * 4 + j) * 4 + ksl) * 32 + lane];
                #pragma unroll
                for (int mf = 0; mf < 4; ++mf)
                    mma16(acc[mf][j], A[mf], bb.x, bb.y);
            }
        }
    }

    #pragma unroll
    for (int j = 0; j < 4; ++j) {
        int col = wk * 32 + j * 8 + kl * 2;
        float b0 = bi[col], b1 = bi[col + 1];
        int ksg = col >> 4;
        int regc = ((col & 15) >= 8) ? 1 : 0;
        int klv  = (col & 7) >> 1;
        #pragma unroll
        for (int mf = 0; mf < 4; ++mf) {
            int r = l0 + wq * 64 + mf * 16 + r4;
            uint32_t h0 = packh2((acc[mf][j].x + b0) * sc, (acc[mf][j].y + b1) * sc);
            uint32_t h1 = packh2((acc[mf][j].z + b0) * sc, (acc[mf][j].w + b1) * sc);
            if (which == 0) {
                int mb = r >> 4;
                int lane_st = r4 * 4 + klv;
                int reg0 = ((r >> 3) & 1) + regc * 2;
                outp[((mb * 16 + ksg) * 32 + lane_st) * 4 + reg0]       = h0;
                outp[((mb * 16 + ksg) * 32 + lane_st) * 4 + (reg0 ^ 1)] = h1;
            } else {
                int lane_st = r4 * 4 + klv;
                int blk = r >> 3;
                outp[((blk * 16 + ksg) * 32 + lane_st) * 2 + regc]         = h0;
                outp[(((blk + 1) * 16 + ksg) * 32 + lane_st) * 2 + regc]   = h1;
            }
        }
    }
}

// ---------------------------------------------------------------------------
// fp16 mma flash attention (R11 config: 16 warps, 2q x 8k, warp tile 64x32):
// half-tile (64KB) K double-buffer — 2 syncs/tile, P·V second MMA chain,
// f16x2 ex2 epilogue. UNCHANGED from the 98.5us version.
// ---------------------------------------------------------------------------
#define OFF_QP   0                         // 64KB
#define OFF_KC0  65536                     // 64KB chunk buffer 0
#define OFF_KC1  131072                    // 64KB chunk buffer 1
#define OFF_VT   196608                    // 2 x 8 cols x 264 halves = 8448B
#define OFF_PD   205056                    // each 4KB: [8][128]
#define OFF_PO0  209152
#define OFF_PO1  213248
#define SMEM_TOTAL 217344

__global__ __launch_bounds__(512) void attn_kernel(
    const float* __restrict__ flow, float* __restrict__ out)
{
    extern __shared__ char smem[];
    const int t    = threadIdx.x;
    const int lane = t & 31;
    const int wid  = t >> 5;
    const int wq   = wid >> 3;
    const int wk   = wid & 7;
    const int b    = blockIdx.y;
    const int l0   = blockIdx.x * 128;

    const uint32_t sb = smem_u32(smem);
    const uint4* Qp4 = (const uint4*)(smem + OFF_QP);
    float* pd  = (float*)(smem + OFF_PD);
    float* po0 = (float*)(smem + OFF_PO0);
    float* po1 = (float*)(smem + OFF_PO1);

    const char* Qpb = reinterpret_cast<const char*>(g_Q) + (size_t)b * NN * CC * 2;
    const char* Kpb = reinterpret_cast<const char*>(g_K) + (size_t)b * NN * CC * 2;

    // Q prologue + first K chunk (tile 0, ksg 0..7), one cp.async group.
    #pragma unroll
    for (int p = 0; p < 8; ++p) {
        int u = t + p * 512;
        cp16(sb + OFF_QP + u * 16, Qpb + (size_t)blockIdx.x * 65536 + u * 16);
    }
    #pragma unroll
    for (int p = 0; p < 8; ++p) {
        int u = t + p * 512;                 // 0..4095: blk = u>>7, 2KB per block
        cp16(sb + OFF_KC0 + u * 16, Kpb + (size_t)(u >> 7) * 4096 + (u & 127) * 16);
    }
    asm volatile("cp.async.commit_group;" ::: "memory");

    const uint32_t kbuf[2] = { sb + OFF_KC0, sb + OFF_KC1 };
    const int r4 = lane >> 2, kl = lane & 3;

    // Persistent output accumulators: cols {o0, o1, d, 0,...}
    float4 acc_o[4];
    #pragma unroll
    for (int mf = 0; mf < 4; ++mf) acc_o[mf] = make_float4(0.f, 0.f, 0.f, 0.f);

    float4 acc[4][4];

    for (int g = 0; g < 2 * NTILE; ++g) {
        const int tile = g >> 1;
        const int half = g & 1;

        if (half == 0) {
            // V store BEFORE this chunk's sync (buffer reuse fenced >=2 syncs back)
            __half* vt = (__half*)(smem + OFF_VT + (tile & 1) * 4224);
            int key = t & 255;
            float v = (t < 256) ? flow[(size_t)b * 2 * NN + tile * STILE + key]
                                : flow[(size_t)b * 2 * NN + NN + tile * STILE + key];
            int c0 = t >> 8;                       // 0 or 1
            vt[c0 * VSTRIDE + key] = __float2half(v);
            vt[(c0 + 2) * VSTRIDE + key] = (c0 == 0) ? __half(1.0f) : __half(0.0f);
            vt[(c0 + 4) * VSTRIDE + key] = __half(0.0f);
            vt[(c0 + 6) * VSTRIDE + key] = __half(0.0f);

            #pragma unroll
            for (int i = 0; i < 4; ++i)
                #pragma unroll
                for (int j = 0; j < 4; ++j)
                    acc[i][j] = make_float4(0.f, 0.f, 0.f, 0.f);
        }

        asm volatile("cp.async.wait_group 0;" ::: "memory");
        __syncthreads();   // chunk g visible; buffer (g+1)&1 free

        if (g < 2 * NTILE - 1) {
            const int gn = g + 1;
            const uint32_t dst = kbuf[gn & 1];
            const char* src = Kpb + (size_t)(gn >> 1) * 131072 + (gn & 1) * 2048;
            #pragma unroll
            for (int p = 0; p < 8; ++p) {
                int u = t + p * 512;
                cp16(dst + u * 16, src + (size_t)(u >> 7) * 4096 + (u & 127) * 16);
            }
            asm volatile("cp.async.commit_group;" ::: "memory");
        }

        const uint2* Ks2 = (const uint2*)(smem + ((g & 1) == 0 ? OFF_KC0 : OFF_KC1));

        #pragma unroll
        for (int ksl = 0; ksl < 8; ++ksl) {
            const int ksg = half * 8 + ksl;
            uint4 A[4];
            #pragma unroll
            for (int mf = 0; mf < 4; ++mf)
                A[mf] = Qp4[((wq * 4 + mf) * 16 + ksg) * 32 + lane];
            #pragma unroll
            for (int j = 0; j < 4; ++j) {
                uint2 bb = Ks2[((wk * 4 + j) * 8 + ksl) * 32 + lane];
                #pragma unroll
                for (int mf = 0; mf < 4; ++mf)
                    mma16(acc[mf][j], A[mf], bb.x, bb.y);
            }
        }

        if (half == 1) {
            // Epilogue: P = ex2(S) in f16x2, P @ Vt via mma (accumulates o0,o1,d)
            const __half* vt = (const __half*)(smem + OFF_VT + (tile & 1) * 4224);
            #pragma unroll
            for (int ks2 = 0; ks2 < 2; ++ks2) {
                int keyb = wk * 32 + ks2 * 16 + kl * 2;
                uint32_t b0 = *reinterpret_cast<const uint32_t*>(&vt[r4 * VSTRIDE + keyb]);
                uint32_t b1 = *reinterpret_cast<const uint32_t*>(&vt[r4 * VSTRIDE + keyb + 8]);
                #pragma unroll
                for (int mf = 0; mf < 4; ++mf) {
                    const float4 sA = acc[mf][2 * ks2];
                    const float4 sB = acc[mf][2 * ks2 + 1];
                    uint4 A;
                    A.x = ex2h2(sA.x, sA.y);
                    A.y = ex2h2(sA.z, sA.w);
                    A.z = ex2h2(sB.x, sB.y);
                    A.w = ex2h2(sB.z, sB.w);
                    mma16(acc_o[mf], A, b0, b1);
                }
            }
        }
    }

    // Final: stash per-warp (o0,o1,d) fragments, merge 8 key-groups, normalize.
    #pragma unroll
    for (int mf = 0; mf < 4; ++mf) {
        int row0 = wq * 64 + mf * 16 + r4;
        if (kl == 0) {
            po0[wk * 128 + row0]     = acc_o[mf].x;
            po1[wk * 128 + row0]     = acc_o[mf].y;
            po0[wk * 128 + row0 + 8] = acc_o[mf].z;
            po1[wk * 128 + row0 + 8] = acc_o[mf].w;
        } else if (kl == 1) {
            pd[wk * 128 + row0]      = acc_o[mf].x;
            pd[wk * 128 + row0 + 8]  = acc_o[mf].z;
        }
    }
    __syncthreads();

    if (t < 128) {
        float D = 0.f, O0 = 0.f, O1 = 0.f;
        #pragma unroll
        for (int g2 = 0; g2 < 8; ++g2) {
            D  += pd[g2 * 128 + t];
            O0 += po0[g2 * 128 + t];
            O1 += po1[g2 * 128 + t];
        }
        float inv = 1.0f / D;
        out[(size_t)b * 2 * NN + l0 + t]      = O0 * inv;
        out[(size_t)b * 2 * NN + NN + l0 + t] = O1 * inv;
    }
}

// ---------------------------------------------------------------------------
extern "C" void kernel_launch(void* const* d_in, const int* in_sizes, int n_in,
                              void* d_out, int out_size)
{
    (void)in_sizes; (void)n_in; (void)out_size;
    const float* feature = (const float*)d_in[0];
    const float* flow    = (const float*)d_in[1];
    const float* q_w     = (const float*)d_in[2];
    const float* q_b     = (const float*)d_in[3];
    const float* k_w     = (const float*)d_in[4];
    const float* k_b     = (const float*)d_in[5];
    float*       out     = (float*)d_out;

    static int configured = 0;
    if (!configured) {
        cudaFuncSetAttribute(attn_kernel, cudaFuncAttributeMaxDynamicSharedMemorySize, SMEM_TOTAL);
        cudaFuncSetAttribute(proj_mma_kernel, cudaFuncAttributeMaxDynamicSharedMemorySize, P_SMEM_TOTAL);
        configured = 1;
    }

    dim3 gp(NN / 128, BB, 2);
    proj_mma_kernel<<<gp, 512, P_SMEM_TOTAL>>>(feature, q_w, q_b, k_w, k_b);

    dim3 g2(NN / 128, BB);
    attn_kernel<<<g2, 512, SMEM_TOTAL>>>(flow, out);
}

// round 17
// speedup vs baseline: 1.0810x; 1.0810x over previous
#include <cuda_runtime.h>
#include <cuda_fp16.h>
#include <cstdint>

#define BB 4
#define CC 256
#define NN 4096
#define STILE 256          // keys per attention tile
#define NTILE (NN / STILE) // 16
#define NCHUNK 4           // k-chunks of 64 per proj tile
#define VSTRIDE 264        // Vt col stride in halves

typedef unsigned long long ull;

// Device-global scratch (no allocations). Q/K/W stored FRAGMENT-PERMUTED fp16.
// Q (A-frag): [b][mb=row/16][ksg=k/16][lane][4xb32], pre-scaled by 1/16*log2e.
// K,W (B-frag): [b][block=row/8][ksg][lane][2xb32].
__device__ __half g_Q[BB * NN * CC];
__device__ __half g_K[BB * NN * CC];
__device__ __half g_W[2 * CC * CC];    // permuted fp16 weights (0=q_w, 1=k_w)

__device__ __forceinline__ void cp16(uint32_t dst, const void* src) {
    asm volatile("cp.async.cg.shared.global [%0], [%1], 16;" :: "r"(dst), "l"(src) : "memory");
}

__device__ __forceinline__ uint32_t smem_u32(const void* p) {
    uint32_t a;
    asm("{ .reg .u64 t; cvta.to.shared.u64 t, %1; cvt.u32.u64 %0, t; }" : "=r"(a) : "l"(p));
    return a;
}

__device__ __forceinline__ void mma16(float4& d, const uint4& a, uint32_t b0, uint32_t b1) {
    asm volatile(
        "mma.sync.aligned.m16n8k16.row.col.f32.f16.f16.f32 "
        "{%0,%1,%2,%3}, {%4,%5,%6,%7}, {%8,%9}, {%0,%1,%2,%3};"
        : "+f"(d.x), "+f"(d.y), "+f"(d.z), "+f"(d.w)
        : "r"(a.x), "r"(a.y), "r"(a.z), "r"(a.w), "r"(b0), "r"(b1));
}

__device__ __forceinline__ uint32_t packh2(float x, float y) {
    __half2 h = __floats2half2_rn(x, y);
    return *reinterpret_cast<uint32_t*>(&h);
}

// pack to fp16 pair then single MUFU ex2 on both halves
__device__ __forceinline__ uint32_t ex2h2(float x, float y) {
    __half2 h = __floats2half2_rn(x, y);
    uint32_t u = *reinterpret_cast<uint32_t*>(&h);
    uint32_t r;
    asm("ex2.approx.f16x2 %0, %1;" : "=r"(r) : "r"(u));
    return r;
}

// ---------------------------------------------------------------------------
// Convert weights: q_w, k_w [d][c] fp32 -> B-fragment-permuted fp16 g_W
// ---------------------------------------------------------------------------
__global__ __launch_bounds__(256) void convert_w_kernel(
    const float* __restrict__ q_w, const float* __restrict__ k_w)
{
    int i = blockIdx.x * 256 + threadIdx.x;          // 0..65535 col-pairs
    int which = i >> 15;
    int rem   = i & 32767;
    int d = rem >> 7;
    int c = (rem & 127) * 2;
    const float* src = which ? k_w : q_w;
    float2 v = *reinterpret_cast<const float2*>(&src[d * CC + c]);
    int block = d >> 3, ksg = c >> 4;
    int reg   = ((c & 15) >= 8) ? 1 : 0;
    int klv   = (c & 7) >> 1;
    int lane  = (d & 7) * 4 + klv;
    uint32_t* wp = reinterpret_cast<uint32_t*>(g_W) + which * 32768;
    wp[((block * 16 + ksg) * 32 + lane) * 2 + reg] = packh2(v.x, v.y);
}

// ---------------------------------------------------------------------------
// Projection via fp16 mma.sync, A fragments built DIRECTLY from fp32 feature
// ([c][n] layout, transpose+convert inline). Writes Q/K fragment-permuted.
// ---------------------------------------------------------------------------
#define P_OFF_AP  0                        // 64KB token fragments
#define P_OFF_W0  65536                    // 32KB
#define P_OFF_W1  98304                    // 32KB
#define P_SMEM_TOTAL 131072

__global__ __launch_bounds__(512) void proj_mma_kernel(
    const float* __restrict__ feature,
    const float* __restrict__ q_b, const float* __restrict__ k_b)
{
    extern __shared__ char smem[];
    const int t    = threadIdx.x;
    const int lane = t & 31;
    const int wid  = t >> 5;
    const int wq   = wid >> 3;
    const int wk   = wid & 7;
    const int b    = blockIdx.y;
    const int l0   = blockIdx.x * 128;
    const int which = blockIdx.z;

    const uint32_t sb = smem_u32(smem);
    uint32_t* Ap32 = (uint32_t*)(smem + P_OFF_AP);
    const uint4* Ap4 = (const uint4*)(smem + P_OFF_AP);

    const float*  Fc = feature + (size_t)b * CC * NN;
    const char*   Wp = reinterpret_cast<const char*>(g_W) + which * 131072;
    const float*  bi = which ? k_b : q_b;
    uint32_t* outp = reinterpret_cast<uint32_t*>((which ? g_K : g_Q) + (size_t)b * NN * CC);
    const float   sc = which ? 1.0f : 0.0625f * 1.4426950408889634f;

    // A fragments from raw fp32 feature: element (row, c) -> fragment slot.
    #pragma unroll
    for (int p = 0; p < 32; ++p) {
        int idx = t + p * 512;        // 0..16383
        int row = idx & 127;
        int c   = (idx >> 7) * 2;     // even c; pair (c, c+1) in one half2
        float f0 = Fc[(size_t)c * NN + l0 + row];
        float f1 = Fc[(size_t)(c + 1) * NN + l0 + row];
        int mb = row >> 4;
        int ks = c >> 4;
        int klv = (c & 7) >> 1;
        int khalf = (c & 15) >> 3;
        int lane_st = (row & 7) * 4 + klv;
        int reg = ((row >> 3) & 1) + khalf * 2;
        Ap32[((mb * 16 + ks) * 32 + lane_st) * 4 + reg] = packh2(f0, f1);
    }

    const uint32_t wbuf[2] = { sb + P_OFF_W0, sb + P_OFF_W1 };
    const int r4 = lane >> 2, kl = lane & 3;

    #pragma unroll
    for (int p = 0; p < 4; ++p) {
        int u = t + p * 512;
        int blk = u >> 6, rm = u & 63;
        cp16(wbuf[0] + u * 16, Wp + blk * 4096 + rm * 16);
    }
    asm volatile("cp.async.commit_group;" ::: "memory");

    float4 acc[4][4];
    #pragma unroll
    for (int i = 0; i < 4; ++i)
        #pragma unroll
        for (int j = 0; j < 4; ++j)
            acc[i][j] = make_float4(0.f, 0.f, 0.f, 0.f);

    for (int c = 0; c < NCHUNK; ++c) {
        asm volatile("cp.async.wait_group 0;" ::: "memory");
        __syncthreads();

        if (c < NCHUNK - 1) {
            const uint32_t dst = wbuf[(c + 1) & 1];
            #pragma unroll
            for (int p = 0; p < 4; ++p) {
                int u = t + p * 512;
                int blk = u >> 6, rm = u & 63;
                cp16(dst + u * 16, Wp + blk * 4096 + (c + 1) * 1024 + rm * 16);
            }
            asm volatile("cp.async.commit_group;" ::: "memory");
        }

        const uint2* Ws2 = (const uint2*)(smem + (((c & 1) == 0) ? P_OFF_W0 : P_OFF_W1));

        #pragma unroll
        for (int ksl = 0; ksl < 4; ++ksl) {
            const int ksg = c * 4 + ksl;
            uint4 A[4];
            #pragma unroll
            for (int mf = 0; mf < 4; ++mf)
                A[mf] = Ap4[((wq * 4 + mf) * 16 + ksg) * 32 + lane];
            #pragma unroll
            for (int j = 0; j < 4; ++j) {
                uint2 bb = Ws2[((wk * 4 + j) * 4 + ksl) * 32 + lane];
                #pragma unroll
                for (int mf = 0; mf < 4; ++mf)
                    mma16(acc[mf][j], A[mf], bb.x, bb.y);
            }
        }
    }

    #pragma unroll
    for (int j = 0; j < 4; ++j) {
        int col = wk * 32 + j * 8 + kl * 2;
        float b0 = bi[col], b1 = bi[col + 1];
        int ksg = col >> 4;
        int regc = ((col & 15) >= 8) ? 1 : 0;
        int klv  = (col & 7) >> 1;
        #pragma unroll
        for (int mf = 0; mf < 4; ++mf) {
            int r = l0 + wq * 64 + mf * 16 + r4;
            uint32_t h0 = packh2((acc[mf][j].x + b0) * sc, (acc[mf][j].y + b1) * sc);
            uint32_t h1 = packh2((acc[mf][j].z + b0) * sc, (acc[mf][j].w + b1) * sc);
            if (which == 0) {
                int mb = r >> 4;
                int lane_st = r4 * 4 + klv;
                int reg0 = ((r >> 3) & 1) + regc * 2;
                outp[((mb * 16 + ksg) * 32 + lane_st) * 4 + reg0]       = h0;
                outp[((mb * 16 + ksg) * 32 + lane_st) * 4 + (reg0 ^ 1)] = h1;
            } else {
                int lane_st = r4 * 4 + klv;
                int blk = r >> 3;
                outp[((blk * 16 + ksg) * 32 + lane_st) * 2 + regc]         = h0;
                outp[(((blk + 1) * 16 + ksg) * 32 + lane_st) * 2 + regc]   = h1;
            }
        }
    }
}

// ---------------------------------------------------------------------------
// fp16 mma flash attention (16 warps, 2q x 8k, warp tile 64x32):
// half-tile (64KB) K double-buffer — 2 syncs/tile, P·V second MMA chain,
// f16x2 ex2 epilogue. The verified 98.5us kernel.
// ---------------------------------------------------------------------------
#define OFF_QP   0                         // 64KB
#define OFF_KC0  65536                     // 64KB chunk buffer 0
#define OFF_KC1  131072                    // 64KB chunk buffer 1
#define OFF_VT   196608                    // 2 x 8 cols x 264 halves = 8448B
#define OFF_PD   205056                    // each 4KB: [8][128]
#define OFF_PO0  209152
#define OFF_PO1  213248
#define SMEM_TOTAL 217344

__global__ __launch_bounds__(512) void attn_kernel(
    const float* __restrict__ flow, float* __restrict__ out)
{
    extern __shared__ char smem[];
    const int t    = threadIdx.x;
    const int lane = t & 31;
    const int wid  = t >> 5;
    const int wq   = wid >> 3;
    const int wk   = wid & 7;
    const int b    = blockIdx.y;
    const int l0   = blockIdx.x * 128;

    const uint32_t sb = smem_u32(smem);
    const uint4* Qp4 = (const uint4*)(smem + OFF_QP);
    float* pd  = (float*)(smem + OFF_PD);
    float* po0 = (float*)(smem + OFF_PO0);
    float* po1 = (float*)(smem + OFF_PO1);

    const char* Qpb = reinterpret_cast<const char*>(g_Q) + (size_t)b * NN * CC * 2;
    const char* Kpb = reinterpret_cast<const char*>(g_K) + (size_t)b * NN * CC * 2;

    // Q prologue + first K chunk (tile 0, ksg 0..7), one cp.async group.
    #pragma unroll
    for (int p = 0; p < 8; ++p) {
        int u = t + p * 512;
        cp16(sb + OFF_QP + u * 16, Qpb + (size_t)blockIdx.x * 65536 + u * 16);
    }
    #pragma unroll
    for (int p = 0; p < 8; ++p) {
        int u = t + p * 512;                 // 0..4095: blk = u>>7, 2KB per block
        cp16(sb + OFF_KC0 + u * 16, Kpb + (size_t)(u >> 7) * 4096 + (u & 127) * 16);
    }
    asm volatile("cp.async.commit_group;" ::: "memory");

    const uint32_t kbuf[2] = { sb + OFF_KC0, sb + OFF_KC1 };
    const int r4 = lane >> 2, kl = lane & 3;

    // Persistent output accumulators: cols {o0, o1, d, 0,...}
    float4 acc_o[4];
    #pragma unroll
    for (int mf = 0; mf < 4; ++mf) acc_o[mf] = make_float4(0.f, 0.f, 0.f, 0.f);

    float4 acc[4][4];

    for (int g = 0; g < 2 * NTILE; ++g) {
        const int tile = g >> 1;
        const int half = g & 1;

        if (half == 0) {
            // V store BEFORE this chunk's sync (buffer reuse fenced >=2 syncs back)
            __half* vt = (__half*)(smem + OFF_VT + (tile & 1) * 4224);
            int key = t & 255;
            float v = (t < 256) ? flow[(size_t)b * 2 * NN + tile * STILE + key]
                                : flow[(size_t)b * 2 * NN + NN + tile * STILE + key];
            int c0 = t >> 8;                       // 0 or 1
            vt[c0 * VSTRIDE + key] = __float2half(v);
            vt[(c0 + 2) * VSTRIDE + key] = (c0 == 0) ? __half(1.0f) : __half(0.0f);
            vt[(c0 + 4) * VSTRIDE + key] = __half(0.0f);
            vt[(c0 + 6) * VSTRIDE + key] = __half(0.0f);

            #pragma unroll
            for (int i = 0; i < 4; ++i)
                #pragma unroll
                for (int j = 0; j < 4; ++j)
                    acc[i][j] = make_float4(0.f, 0.f, 0.f, 0.f);
        }

        asm volatile("cp.async.wait_group 0;" ::: "memory");
        __syncthreads();   // chunk g visible; buffer (g+1)&1 free

        if (g < 2 * NTILE - 1) {
            const int gn = g + 1;
            const uint32_t dst = kbuf[gn & 1];
            const char* src = Kpb + (size_t)(gn >> 1) * 131072 + (gn & 1) * 2048;
            #pragma unroll
            for (int p = 0; p < 8; ++p) {
                int u = t + p * 512;
                cp16(dst + u * 16, src + (size_t)(u >> 7) * 4096 + (u & 127) * 16);
            }
            asm volatile("cp.async.commit_group;" ::: "memory");
        }

        const uint2* Ks2 = (const uint2*)(smem + ((g & 1) == 0 ? OFF_KC0 : OFF_KC1));

        #pragma unroll
        for (int ksl = 0; ksl < 8; ++ksl) {
            const int ksg = half * 8 + ksl;
            uint4 A[4];
            #pragma unroll
            for (int mf = 0; mf < 4; ++mf)
                A[mf] = Qp4[((wq * 4 + mf) * 16 + ksg) * 32 + lane];
            #pragma unroll
            for (int j = 0; j < 4; ++j) {
                uint2 bb = Ks2[((wk * 4 + j) * 8 + ksl) * 32 + lane];
                #pragma unroll
                for (int mf = 0; mf < 4; ++mf)
                    mma16(acc[mf][j], A[mf], bb.x, bb.y);
            }
        }

        if (half == 1) {
            // Epilogue: P = ex2(S) in f16x2, P @ Vt via mma (accumulates o0,o1,d)
            const __half* vt = (const __half*)(smem + OFF_VT + (tile & 1) * 4224);
            #pragma unroll
            for (int ks2 = 0; ks2 < 2; ++ks2) {
                int keyb = wk * 32 + ks2 * 16 + kl * 2;
                uint32_t b0 = *reinterpret_cast<const uint32_t*>(&vt[r4 * VSTRIDE + keyb]);
                uint32_t b1 = *reinterpret_cast<const uint32_t*>(&vt[r4 * VSTRIDE + keyb + 8]);
                #pragma unroll
                for (int mf = 0; mf < 4; ++mf) {
                    const float4 sA = acc[mf][2 * ks2];
                    const float4 sB = acc[mf][2 * ks2 + 1];
                    uint4 A;
                    A.x = ex2h2(sA.x, sA.y);
                    A.y = ex2h2(sA.z, sA.w);
                    A.z = ex2h2(sB.x, sB.y);
                    A.w = ex2h2(sB.z, sB.w);
                    mma16(acc_o[mf], A, b0, b1);
                }
            }
        }
    }

    // Final: stash per-warp (o0,o1,d) fragments, merge 8 key-groups, normalize.
    #pragma unroll
    for (int mf = 0; mf < 4; ++mf) {
        int row0 = wq * 64 + mf * 16 + r4;
        if (kl == 0) {
            po0[wk * 128 + row0]     = acc_o[mf].x;
            po1[wk * 128 + row0]     = acc_o[mf].y;
            po0[wk * 128 + row0 + 8] = acc_o[mf].z;
            po1[wk * 128 + row0 + 8] = acc_o[mf].w;
        } else if (kl == 1) {
            pd[wk * 128 + row0]      = acc_o[mf].x;
            pd[wk * 128 + row0 + 8]  = acc_o[mf].z;
        }
    }
    __syncthreads();

    if (t < 128) {
        float D = 0.f, O0 = 0.f, O1 = 0.f;
        #pragma unroll
        for (int g2 = 0; g2 < 8; ++g2) {
            D  += pd[g2 * 128 + t];
            O0 += po0[g2 * 128 + t];
            O1 += po1[g2 * 128 + t];
        }
        float inv = 1.0f / D;
        out[(size_t)b * 2 * NN + l0 + t]      = O0 * inv;
        out[(size_t)b * 2 * NN + NN + l0 + t] = O1 * inv;
    }
}

// ---------------------------------------------------------------------------
extern "C" void kernel_launch(void* const* d_in, const int* in_sizes, int n_in,
                              void* d_out, int out_size)
{
    (void)in_sizes; (void)n_in; (void)out_size;
    const float* feature = (const float*)d_in[0];
    const float* flow    = (const float*)d_in[1];
    const float* q_w     = (const float*)d_in[2];
    const float* q_b     = (const float*)d_in[3];
    const float* k_w     = (const float*)d_in[4];
    const float* k_b     = (const float*)d_in[5];
    float*       out     = (float*)d_out;

    static int configured = 0;
    if (!configured) {
        cudaFuncSetAttribute(attn_kernel, cudaFuncAttributeMaxDynamicSharedMemorySize, SMEM_TOTAL);
        cudaFuncSetAttribute(proj_mma_kernel, cudaFuncAttributeMaxDynamicSharedMemorySize, P_SMEM_TOTAL);
        configured = 1;
    }

    convert_w_kernel<<<256, 256>>>(q_w, k_w);

    dim3 gp(NN / 128, BB, 2);
    proj_mma_kernel<<<gp, 512, P_SMEM_TOTAL>>>(feature, q_b, k_b);

    dim3 g2(NN / 128, BB);
    attn_kernel<<<g2, 512, SMEM_TOTAL>>>(flow, out);
}